// round 8
// baseline (speedup 1.0000x reference)
#include <cuda_runtime.h>
#include <math.h>

#define TT     256   // B*S tiles
#define NTOK   256   // N tokens per tile
#define DMODEL 512
#define NH     8
#define HD     64

// ---------------- scratch (device globals: no allocation allowed) -----------
__device__ float g_Q[TT * DMODEL];          // q per tile (with bias)
__device__ float g_P[TT * NH * DMODEL];     // [t][h][d], pre-scaled by 1/8
__device__ float g_Y[TT * NH * DMODEL];     // [t][h][d], softmax-weighted x sums
__device__ float g_ctx[TT * DMODEL];        // concat heads per tile

// ---------------- generic 16x64-tile GEMM: C = A @ B + bias -----------------
// C[(t0+ty)*c_stride + coff + n0 + 4*tx + c] for 16 rows x 64 cols per CTA.
__global__ __launch_bounds__(256) void gemm_k(
    const float* __restrict__ A, size_t a_stride, size_t a_zoff,
    const float* __restrict__ B, int b_stride, int b_zoff,
    const float* __restrict__ bias, int bias_zoff,
    float* __restrict__ C, int c_stride, int c_zoff,
    int Kdim)
{
    __shared__ float As[16 * 32];
    __shared__ float Bs[32 * 64];
    int tid = threadIdx.x;
    int tx = tid & 15, ty = tid >> 4;
    int t0 = blockIdx.x * 16;
    int n0 = blockIdx.y * 64;
    int z  = blockIdx.z;

    const float* Ab    = A + (size_t)z * a_zoff;
    const float* Bb    = B + (size_t)z * b_zoff + n0;
    const float* biasb = bias + (size_t)z * bias_zoff + n0;
    float*       Cb    = C + (size_t)z * c_zoff + n0;

    float4 acc = make_float4(0.f, 0.f, 0.f, 0.f);

    for (int k0 = 0; k0 < Kdim; k0 += 32) {
        __syncthreads();
        // stage A: 16 rows x 32 k (512 elems, 2/thread), coalesced along k
        {
            int i = tid;
            int r = i >> 5, kk = i & 31;
            As[i] = Ab[(size_t)(t0 + r) * a_stride + k0 + kk];
            i += 256; r = i >> 5; kk = i & 31;
            As[i] = Ab[(size_t)(t0 + r) * a_stride + k0 + kk];
        }
        // stage B: 32 k x 64 n (2048 elems, 8/thread), coalesced along n
        #pragma unroll
        for (int it = 0; it < 8; it++) {
            int i = tid + it * 256;
            int r = i >> 6, c = i & 63;
            Bs[i] = Bb[(size_t)(k0 + r) * b_stride + c];
        }
        __syncthreads();
        #pragma unroll
        for (int kk = 0; kk < 32; kk++) {
            float a  = As[ty * 32 + kk];                       // broadcast
            float4 b = *reinterpret_cast<const float4*>(&Bs[kk * 64 + tx * 4]);
            acc.x += a * b.x; acc.y += a * b.y;
            acc.z += a * b.z; acc.w += a * b.w;
        }
    }
    float4 bb = *reinterpret_cast<const float4*>(&biasb[tx * 4]);
    float4 o  = make_float4(acc.x + bb.x, acc.y + bb.y, acc.z + bb.z, acc.w + bb.w);
    *reinterpret_cast<float4*>(&Cb[(size_t)(t0 + ty) * c_stride + tx * 4]) = o;
}

// ---------------- K2: P[t,h,d] = 0.125 * sum_j Q[t,h*64+j] * Wk[d, h*64+j] --
// C = A @ B^T with K=64 per head. Tile 16t x 64d per CTA.
__global__ __launch_bounds__(256) void pproj_k(const float* __restrict__ Wk)
{
    __shared__ float As[16 * 64];
    __shared__ float Bt[64 * 68];   // transposed Wk slice, padded (272B rows)
    int tid = threadIdx.x;
    int tx = tid & 15, ty = tid >> 4;
    int t0 = blockIdx.x * 16;
    int d0 = blockIdx.y * 64;
    int h  = blockIdx.z;

    #pragma unroll
    for (int it = 0; it < 4; it++) {
        int i = tid + it * 256;
        int r = i >> 6, j = i & 63;
        As[i] = g_Q[(size_t)(t0 + r) * DMODEL + h * HD + j];
    }
    #pragma unroll
    for (int it = 0; it < 16; it++) {
        int i = tid + it * 256;
        int dd = i >> 6, j = i & 63;
        Bt[j * 68 + dd] = Wk[(size_t)(d0 + dd) * DMODEL + h * HD + j];
    }
    __syncthreads();

    float4 acc = make_float4(0.f, 0.f, 0.f, 0.f);
    #pragma unroll
    for (int j = 0; j < 64; j++) {
        float a  = As[ty * 64 + j];                            // broadcast
        float4 b = *reinterpret_cast<const float4*>(&Bt[j * 68 + tx * 4]);
        acc.x += a * b.x; acc.y += a * b.y;
        acc.z += a * b.z; acc.w += a * b.w;
    }
    const float s = 0.125f;  // 1/sqrt(depth)
    float4 o = make_float4(acc.x * s, acc.y * s, acc.z * s, acc.w * s);
    *reinterpret_cast<float4*>(
        &g_P[((size_t)(t0 + ty) * NH + h) * DMODEL + d0 + tx * 4]) = o;
}

// ---------------- K3: per-tile attention: logits -> softmax -> Y ------------
__global__ __launch_bounds__(256) void attn_k(const float* __restrict__ x,
                                              const float* __restrict__ bk)
{
    __shared__ float Ps[DMODEL * NH];     // 16 KB: P staged as [d][h]
    __shared__ float xs[16 * 257];        // 16.4 KB: transposed x chunk; later
                                          // aliased as Ls[0:2048] / Es[2048:4096]
    __shared__ float red[16];             // c-terms -> max -> inv-sum
    int tid = threadIdx.x;
    int t = blockIdx.x;
    const float* xt = x + (size_t)t * NTOK * DMODEL;

    // stage P: g_P[t][h][d] -> Ps[d*8+h]
    #pragma unroll
    for (int it = 0; it < 16; it++) {
        int i = tid + it * 256;
        int h = i >> 9, d = i & 511;
        Ps[d * 8 + h] = g_P[((size_t)t * NH + h) * DMODEL + d];
    }
    // c[h] = 0.125 * q_h . bk_h   (warp per head)
    {
        int h = tid >> 5, j = tid & 31;
        const float* Qt  = g_Q + (size_t)t * DMODEL + h * HD;
        const float* bkh = bk + h * HD;
        float p = Qt[j] * bkh[j] + Qt[j + 32] * bkh[j + 32];
        #pragma unroll
        for (int o = 16; o > 0; o >>= 1) p += __shfl_down_sync(0xffffffffu, p, o);
        if (j == 0) red[h] = 0.125f * p;
    }
    __syncthreads();

    float l[8];
    #pragma unroll
    for (int h = 0; h < 8; h++) l[h] = red[h];

    // ---- phase 1: logits l[h] = c[h] + sum_d x[n,d] * P[d,h]  (row n = tid)
    int n = tid;
    for (int c0 = 0; c0 < DMODEL; c0 += 16) {
        __syncthreads();
        // stage transposed chunk: coalesced float4 gmem reads -> xs[dl][n]
        #pragma unroll
        for (int it = 0; it < 4; it++) {
            int i = tid + it * 256;
            int row = i >> 2, f4 = i & 3;
            float4 v = reinterpret_cast<const float4*>(
                           xt + (size_t)row * DMODEL + c0)[f4];
            int dl = f4 * 4;
            xs[(dl + 0) * 257 + row] = v.x;
            xs[(dl + 1) * 257 + row] = v.y;
            xs[(dl + 2) * 257 + row] = v.z;
            xs[(dl + 3) * 257 + row] = v.w;
        }
        __syncthreads();
        #pragma unroll
        for (int dl = 0; dl < 16; dl++) {
            float xv = xs[dl * 257 + n];                        // conflict-free
            const float4* Pp = reinterpret_cast<const float4*>(Ps + (c0 + dl) * 8);
            float4 p0 = Pp[0], p1 = Pp[1];                      // broadcast
            l[0] += xv * p0.x; l[1] += xv * p0.y;
            l[2] += xv * p0.z; l[3] += xv * p0.w;
            l[4] += xv * p1.x; l[5] += xv * p1.y;
            l[6] += xv * p1.z; l[7] += xv * p1.w;
        }
    }
    __syncthreads();

    // ---- softmax (xs dead: alias as Ls / Es)
    float* Ls = xs;          // [n][h] logits
    float* Es = xs + 2048;   // [h][n] exp values
    #pragma unroll
    for (int h = 0; h < 8; h++) Ls[n * 8 + h] = l[h];
    __syncthreads();

    int wid = tid >> 5, lane = tid & 31;
    {   // max per head (warp per head)
        float m = -1e30f;
        for (int i = lane; i < 256; i += 32) m = fmaxf(m, Ls[i * 8 + wid]);
        #pragma unroll
        for (int o = 16; o > 0; o >>= 1)
            m = fmaxf(m, __shfl_xor_sync(0xffffffffu, m, o));
        if (lane == 0) red[wid] = m;
    }
    __syncthreads();
    #pragma unroll
    for (int h = 0; h < 8; h++) Es[h * 256 + n] = __expf(l[h] - red[h]);
    __syncthreads();
    {   // sum per head -> 1/s
        float s = 0.f;
        for (int i = lane; i < 256; i += 32) s += Es[wid * 256 + i];
        #pragma unroll
        for (int o = 16; o > 0; o >>= 1) s += __shfl_xor_sync(0xffffffffu, s, o);
        if (lane == 0) red[8 + wid] = 1.0f / s;
    }
    __syncthreads();

    // ---- phase 2: Y[h,d] = (1/s) sum_n e[h,n] x[n,d]; thread owns 2 cols
    float acc[16];
    #pragma unroll
    for (int i = 0; i < 16; i++) acc[i] = 0.f;
    const float2* x2 = reinterpret_cast<const float2*>(xt) + tid;  // cols 2t,2t+1
    #pragma unroll 4
    for (int nn = 0; nn < NTOK; nn++) {
        float2 xv = x2[(size_t)nn * 256];        // coalesced, L2-hit
        #pragma unroll
        for (int h = 0; h < 8; h++) {
            float ev = Es[h * 256 + nn];         // broadcast
            acc[h * 2]     += ev * xv.x;
            acc[h * 2 + 1] += ev * xv.y;
        }
    }
    #pragma unroll
    for (int h = 0; h < 8; h++) {
        float inv = red[8 + h];
        float2 o;
        o.x = acc[h * 2] * inv;
        o.y = acc[h * 2 + 1] * inv;
        reinterpret_cast<float2*>(g_Y + ((size_t)t * NH + h) * DMODEL)[tid] = o;
    }
}

// ---------------------------------------------------------------------------
extern "C" void kernel_launch(void* const* d_in, const int* in_sizes, int n_in,
                              void* d_out, int out_size)
{
    const float* x  = (const float*)d_in[0];
    const float* Wq = (const float*)d_in[1];
    const float* bq = (const float*)d_in[2];
    const float* Wk = (const float*)d_in[3];
    const float* bk = (const float*)d_in[4];
    const float* Wv = (const float*)d_in[5];
    const float* bv = (const float*)d_in[6];
    const float* Wo = (const float*)d_in[7];
    const float* bo = (const float*)d_in[8];
    float* out = (float*)d_out;
    (void)in_sizes; (void)n_in; (void)out_size;

    void *pQ, *pY, *pC;
    cudaGetSymbolAddress(&pQ, g_Q);
    cudaGetSymbolAddress(&pY, g_Y);
    cudaGetSymbolAddress(&pC, g_ctx);

    // K1: Q = X0 @ Wq + bq   (A rows are the n=0 token of each tile)
    gemm_k<<<dim3(16, 8, 1), 256>>>(
        x, (size_t)(NTOK * DMODEL), 0,
        Wq, DMODEL, 0, bq, 0,
        (float*)pQ, DMODEL, 0, DMODEL);

    // K2: P[t,h,d] (pre-scaled by 1/8)
    pproj_k<<<dim3(16, 8, NH), 256>>>(Wk);

    // K3: per-tile attention -> g_Y
    attn_k<<<TT, 256>>>(x, bk);

    // K4: ctx_h = Y_h @ Wv[:,h] + bv_h   (per-head via blockIdx.z offsets)
    gemm_k<<<dim3(16, 1, NH), 256>>>(
        (const float*)pY, (size_t)(NH * DMODEL), (size_t)DMODEL,
        Wv, DMODEL, HD, bv, HD,
        (float*)pC, DMODEL, HD, DMODEL);

    // K5: out = ctx @ Wo + bo
    gemm_k<<<dim3(16, 8, 1), 256>>>(
        (const float*)pC, (size_t)DMODEL, 0,
        Wo, DMODEL, 0, bo, 0,
        out, DMODEL, 0, DMODEL);
}